// round 9
// baseline (speedup 1.0000x reference)
#include <cuda_runtime.h>
#include <cuda_bf16.h>
#include <cstdint>

#define NTOK   8192     // 8 * 1024 tokens
#define DMODEL 1024
#define NQKV   512      // H * D_K
#define SEQ    1024
#define NHEAD  8
#define DHEAD  64

// -------------------- scratch (device globals: allocation-guard safe) ----------
__device__ __nv_bfloat16 g_xh[NTOK * DMODEL], g_xl[NTOK * DMODEL];
__device__ __nv_bfloat16 g_qb[NTOK * NQKV],  g_kb[NTOK * NQKV];
__device__ __nv_bfloat16 g_vh[NTOK * NQKV],  g_vl[NTOK * NQKV];
__device__ __nv_bfloat16 g_aoh[NTOK * NQKV], g_aol[NTOK * NQKV];
__device__ __nv_bfloat16 g_wqh[NQKV * DMODEL], g_wql[NQKV * DMODEL];
__device__ __nv_bfloat16 g_wkh[NQKV * DMODEL], g_wkl[NQKV * DMODEL];
__device__ __nv_bfloat16 g_wvh[NQKV * DMODEL], g_wvl[NQKV * DMODEL];
__device__ __nv_bfloat16 g_woh[DMODEL * NQKV], g_wol[DMODEL * NQKV];

extern __shared__ unsigned char dynsmem[];

// -------------------- PTX helpers (base-target sm_80+ instructions) ------------
__device__ __forceinline__ uint32_t smem_to_u32(const void* p) {
    uint32_t a;
    asm("{ .reg .u64 t; cvta.to.shared.u64 t, %1; cvt.u32.u64 %0, t; }"
        : "=r"(a) : "l"(p));
    return a;
}
__device__ __forceinline__ void cp16(uint32_t dst, const void* src) {
    asm volatile("cp.async.ca.shared.global [%0], [%1], 16;"
                 :: "r"(dst), "l"(src) : "memory");
}
#define CP_COMMIT() asm volatile("cp.async.commit_group;" ::: "memory")
#define CP_WAIT2()  asm volatile("cp.async.wait_group 2;" ::: "memory")
#define CP_WAIT1()  asm volatile("cp.async.wait_group 1;" ::: "memory")
#define CP_WAIT0()  asm volatile("cp.async.wait_group 0;" ::: "memory")

__device__ __forceinline__ void ldsm_x4(uint32_t* r, uint32_t addr) {
    asm volatile("ldmatrix.sync.aligned.m8n8.x4.shared.b16 {%0,%1,%2,%3}, [%4];"
                 : "=r"(r[0]), "=r"(r[1]), "=r"(r[2]), "=r"(r[3]) : "r"(addr));
}
__device__ __forceinline__ void ldsm_x2(uint32_t* r, uint32_t addr) {
    asm volatile("ldmatrix.sync.aligned.m8n8.x2.shared.b16 {%0,%1}, [%2];"
                 : "=r"(r[0]), "=r"(r[1]) : "r"(addr));
}
__device__ __forceinline__ void ldsm_x2t(uint32_t* r, uint32_t addr) {
    asm volatile("ldmatrix.sync.aligned.m8n8.x2.trans.shared.b16 {%0,%1}, [%2];"
                 : "=r"(r[0]), "=r"(r[1]) : "r"(addr));
}
__device__ __forceinline__ void mma16816(float* c, const uint32_t* a, const uint32_t* b) {
    asm volatile("mma.sync.aligned.m16n8k16.row.col.f32.bf16.bf16.f32 "
                 "{%0,%1,%2,%3}, {%4,%5,%6,%7}, {%8,%9}, {%0,%1,%2,%3};"
                 : "+f"(c[0]), "+f"(c[1]), "+f"(c[2]), "+f"(c[3])
                 : "r"(a[0]), "r"(a[1]), "r"(a[2]), "r"(a[3]),
                   "r"(b[0]), "r"(b[1]));
}
__device__ __forceinline__ uint32_t pkbf2(float lo, float hi) {
    __nv_bfloat162 t = __floats2bfloat162_rn(lo, hi);
    return reinterpret_cast<uint32_t&>(t);
}

// -------------------- pre-pass: split fp32 -> bf16 hi/lo -----------------------
__global__ void split_kernel(const float* __restrict__ src,
                             __nv_bfloat16* __restrict__ hi,
                             __nv_bfloat16* __restrict__ lo, int n2) {
    int i = blockIdx.x * blockDim.x + threadIdx.x;
    if (i < n2) {
        float2 v = ((const float2*)src)[i];
        __nv_bfloat16 h0 = __float2bfloat16(v.x);
        __nv_bfloat16 h1 = __float2bfloat16(v.y);
        __nv_bfloat16 l0 = __float2bfloat16(v.x - __bfloat162float(h0));
        __nv_bfloat16 l1 = __float2bfloat16(v.y - __bfloat162float(h1));
        ((__nv_bfloat162*)hi)[i] = __halves2bfloat162(h0, h1);
        ((__nv_bfloat162*)lo)[i] = __halves2bfloat162(l0, l1);
    }
}

// -------------------- pre-pass: W[K,N] fp32 -> Wt[N,K] bf16 hi/lo --------------
__global__ void transpose_split3(const float* __restrict__ W0, __nv_bfloat16* __restrict__ T0h,
                                 __nv_bfloat16* __restrict__ T0l,
                                 const float* __restrict__ W1, __nv_bfloat16* __restrict__ T1h,
                                 __nv_bfloat16* __restrict__ T1l,
                                 const float* __restrict__ W2, __nv_bfloat16* __restrict__ T2h,
                                 __nv_bfloat16* __restrict__ T2l,
                                 int Kd, int Nd) {
    __shared__ float t[32][33];
    const float* W = (blockIdx.z == 0) ? W0 : (blockIdx.z == 1) ? W1 : W2;
    __nv_bfloat16* Th = (blockIdx.z == 0) ? T0h : (blockIdx.z == 1) ? T1h : T2h;
    __nv_bfloat16* Tl = (blockIdx.z == 0) ? T0l : (blockIdx.z == 1) ? T1l : T2l;
    int k0 = blockIdx.y * 32, n0 = blockIdx.x * 32;
    for (int i = threadIdx.y; i < 32; i += 8)
        t[i][threadIdx.x] = W[(size_t)(k0 + i) * Nd + n0 + threadIdx.x];
    __syncthreads();
    for (int i = threadIdx.y; i < 32; i += 8) {
        float v = t[threadIdx.x][i];
        __nv_bfloat16 h = __float2bfloat16(v);
        __nv_bfloat16 l = __float2bfloat16(v - __bfloat162float(h));
        size_t o = (size_t)(n0 + i) * Kd + k0 + threadIdx.x;
        Th[o] = h; Tl[o] = l;
    }
}

// -------------------- bf16x3 HMMA GEMM: C = A[M,K] @ B[N,K]^T + bias -----------
// CTA tile 256x128, BK=32, 512 threads = 16 warps of 64x32, 3-stage cp.async.
// smem rows padded to 80 B: conflict-free ldmatrix (20-bank stride).
// OM=0: fp32 out. OM=1: bf16 out. OM=2: bf16 hi/lo out.
#define GROWB     80
#define OFF_AL    (256 * GROWB)               // 20480
#define OFF_BH    (2 * 256 * GROWB)           // 40960
#define OFF_BL    (OFF_BH + 128 * GROWB)      // 51200
#define GSTAGE    (OFF_BH + 2 * 128 * GROWB)  // 61440 per stage
#define GSM_TOTAL (3 * GSTAGE)                // 184320

template <int OM>
__global__ __launch_bounds__(512, 1)
void gemm_bf16x3(const __nv_bfloat16* __restrict__ Ah, const __nv_bfloat16* __restrict__ Al,
                 const __nv_bfloat16* __restrict__ Bh, const __nv_bfloat16* __restrict__ Bl,
                 const float* __restrict__ bias, float* __restrict__ Cf,
                 __nv_bfloat16* __restrict__ Ch, __nv_bfloat16* __restrict__ Cl,
                 int K, int N) {
    const uint32_t smem_base = smem_to_u32(dynsmem);
    const int tid  = threadIdx.x;
    const int wid  = tid >> 5, lane = tid & 31;
    const int m0 = blockIdx.y * 256, n0 = blockIdx.x * 128;

    // ---- loader: thread -> r0 = tid>>2 (0..127), seg = tid&3 (16B column) ----
    const int r0  = tid >> 2, seg = tid & 3;
    const size_t rstep = (size_t)128 * K;
    const __nv_bfloat16* pAh = Ah + (size_t)(m0 + r0) * K + seg * 8;
    const __nv_bfloat16* pAl = Al + (size_t)(m0 + r0) * K + seg * 8;
    const __nv_bfloat16* pBh = Bh + (size_t)(n0 + r0) * K + seg * 8;
    const __nv_bfloat16* pBl = Bl + (size_t)(n0 + r0) * K + seg * 8;
    const uint32_t dRow = r0 * GROWB + seg * 16;

    // ---- compute mapping: 16 warps = 4 (m) x 4 (n), 64x32 each ----
    const int wm = (wid & 3) * 64;
    const int wn = (wid >> 2) * 32;
    const int aRowOff = lane & 15;
    const int aColOff = (lane & 16) ? 8 : 0;
    const int bRowOff = lane & 7;
    const int bColOff = (lane & 8) ? 8 : 0;

    float acc[4][4][4];
#pragma unroll
    for (int i = 0; i < 4; i++)
#pragma unroll
        for (int j = 0; j < 4; j++)
#pragma unroll
            for (int c = 0; c < 4; c++) acc[i][j][c] = 0.0f;

    const int nstage = K >> 5;

    auto issue = [&](int s) {
        const uint32_t bb = smem_base + (uint32_t)(s % 3) * GSTAGE;
        const int k0 = s << 5;
        cp16(bb + dRow,                    pAh + k0);
        cp16(bb + dRow + 128 * GROWB,      pAh + rstep + k0);
        cp16(bb + OFF_AL + dRow,           pAl + k0);
        cp16(bb + OFF_AL + dRow + 128 * GROWB, pAl + rstep + k0);
        cp16(bb + OFF_BH + dRow,           pBh + k0);
        cp16(bb + OFF_BL + dRow,           pBl + k0);
        CP_COMMIT();
    };

    issue(0);
    issue(1);

    for (int s = 0; s < nstage; ++s) {
        if (s + 2 < nstage) { issue(s + 2); CP_WAIT2(); }
        else if (s + 1 < nstage) { CP_WAIT1(); }
        else { CP_WAIT0(); }
        __syncthreads();

        const uint32_t sb = smem_base + (uint32_t)(s % 3) * GSTAGE;
#pragma unroll
        for (int kc = 0; kc < 32; kc += 16) {
            uint32_t ah[4][4], al[4][4];
#pragma unroll
            for (int i = 0; i < 4; ++i) {
                uint32_t addr = sb + (wm + 16 * i + aRowOff) * GROWB
                                   + (kc + aColOff) * 2;
                ldsm_x4(ah[i], addr);
                ldsm_x4(al[i], addr + OFF_AL);
            }
#pragma unroll
            for (int j = 0; j < 4; ++j) {
                uint32_t bh2[2], bl2[2];
                uint32_t addr = sb + OFF_BH + (wn + 8 * j + bRowOff) * GROWB
                                   + (kc + bColOff) * 2;
                ldsm_x2(bh2, addr);
                ldsm_x2(bl2, addr + 128 * GROWB);
#pragma unroll
                for (int i = 0; i < 4; ++i) {
                    mma16816(acc[i][j], ah[i], bh2);
                    mma16816(acc[i][j], ah[i], bl2);
                    mma16816(acc[i][j], al[i], bh2);
                }
            }
        }
        __syncthreads();
    }

    // ---- epilogue ----
    const int er = lane >> 2;
    const int ec = (lane & 3) * 2;
#pragma unroll
    for (int j = 0; j < 4; ++j) {
        const int n = n0 + wn + 8 * j + ec;
        const float b0 = bias[n], b1 = bias[n + 1];
#pragma unroll
        for (int i = 0; i < 4; ++i) {
            const int m = m0 + wm + 16 * i + er;
            float v0 = acc[i][j][0] + b0, v1 = acc[i][j][1] + b1;
            float v2 = acc[i][j][2] + b0, v3 = acc[i][j][3] + b1;
            if (OM == 0) {
                *(float2*)(Cf + (size_t)m * N + n)       = make_float2(v0, v1);
                *(float2*)(Cf + (size_t)(m + 8) * N + n) = make_float2(v2, v3);
            } else {
                __nv_bfloat16 h0 = __float2bfloat16(v0), h1 = __float2bfloat16(v1);
                __nv_bfloat16 h2 = __float2bfloat16(v2), h3 = __float2bfloat16(v3);
                *(__nv_bfloat162*)(Ch + (size_t)m * N + n) = __halves2bfloat162(h0, h1);
                *(__nv_bfloat162*)(Ch + (size_t)(m + 8) * N + n) = __halves2bfloat162(h2, h3);
                if (OM == 2) {
                    __nv_bfloat16 l0 = __float2bfloat16(v0 - __bfloat162float(h0));
                    __nv_bfloat16 l1 = __float2bfloat16(v1 - __bfloat162float(h1));
                    __nv_bfloat16 l2 = __float2bfloat16(v2 - __bfloat162float(h2));
                    __nv_bfloat16 l3 = __float2bfloat16(v3 - __bfloat162float(h3));
                    *(__nv_bfloat162*)(Cl + (size_t)m * N + n) = __halves2bfloat162(l0, l1);
                    *(__nv_bfloat162*)(Cl + (size_t)(m + 8) * N + n) = __halves2bfloat162(l2, l3);
                }
            }
        }
    }
}

// -------------------- HMMA flash attention (validated R7) ----------------------
#define ASTR 72   // bf16 per smem row

__global__ __launch_bounds__(128)
void attn_mma(const __nv_bfloat16* __restrict__ Qb, const __nv_bfloat16* __restrict__ Kb,
              const __nv_bfloat16* __restrict__ Vhg, const __nv_bfloat16* __restrict__ Vlg,
              __nv_bfloat16* __restrict__ AOh, __nv_bfloat16* __restrict__ AOl) {
    __shared__ __align__(16) __nv_bfloat16 Qs[64 * ASTR];
    __shared__ __align__(16) __nv_bfloat16 Ks[64 * ASTR];
    __shared__ __align__(16) __nv_bfloat16 Vhs[64 * ASTR];
    __shared__ __align__(16) __nv_bfloat16 Vls[64 * ASTR];

    const int tid = threadIdx.x, wid = tid >> 5, lane = tid & 31;
    const int q0 = blockIdx.x * 64, h = blockIdx.y, b = blockIdx.z;
    const size_t rowbase = (size_t)b * SEQ;
    const int coff = h * DHEAD;

    const int lr = tid >> 1, lc = (tid & 1) * 32;
    {
        const __nv_bfloat16* src = Qb + (rowbase + q0 + lr) * NQKV + coff + lc;
#pragma unroll
        for (int c = 0; c < 4; ++c)
            *(uint4*)&Qs[lr * ASTR + lc + 8 * c] = *(const uint4*)(src + 8 * c);
    }
    __syncthreads();

    const uint32_t qbase = smem_to_u32(Qs), kbase = smem_to_u32(Ks);
    const uint32_t vhb = smem_to_u32(Vhs), vlb = smem_to_u32(Vls);
    const int wq = wid * 16;

    uint32_t qf[4][4];
#pragma unroll
    for (int ks = 0; ks < 4; ++ks)
        ldsm_x4(qf[ks], qbase + ((wq + (lane & 15)) * ASTR + ks * 16
                                 + ((lane & 16) ? 8 : 0)) * 2);

    float oacc[8][4];
#pragma unroll
    for (int j = 0; j < 8; ++j)
#pragma unroll
        for (int c = 0; c < 4; ++c) oacc[j][c] = 0.0f;
    float mrow0 = -1e30f, mrow1 = -1e30f, lrow0 = 0.0f, lrow1 = 0.0f;

    for (int kv0 = 0; kv0 < SEQ; kv0 += 64) {
        __syncthreads();
        {
            const size_t grow = (rowbase + kv0 + lr) * NQKV + coff + lc;
            const int so = lr * ASTR + lc;
#pragma unroll
            for (int c = 0; c < 4; ++c) {
                *(uint4*)&Ks[so + 8 * c]  = *(const uint4*)(Kb  + grow + 8 * c);
                *(uint4*)&Vhs[so + 8 * c] = *(const uint4*)(Vhg + grow + 8 * c);
                *(uint4*)&Vls[so + 8 * c] = *(const uint4*)(Vlg + grow + 8 * c);
            }
        }
        __syncthreads();

        float s[8][4];
#pragma unroll
        for (int j = 0; j < 8; ++j)
#pragma unroll
            for (int c = 0; c < 4; ++c) s[j][c] = 0.0f;
#pragma unroll
        for (int ks = 0; ks < 4; ++ks)
#pragma unroll
            for (int j = 0; j < 8; ++j) {
                uint32_t kf[2];
                ldsm_x2(kf, kbase + ((8 * j + (lane & 7)) * ASTR + ks * 16
                                     + ((lane & 8) ? 8 : 0)) * 2);
                mma16816(s[j], qf[ks], kf);
            }

        float tmax0 = -1e30f, tmax1 = -1e30f;
#pragma unroll
        for (int j = 0; j < 8; ++j) {
            s[j][0] *= 0.125f; s[j][1] *= 0.125f; s[j][2] *= 0.125f; s[j][3] *= 0.125f;
            tmax0 = fmaxf(tmax0, fmaxf(s[j][0], s[j][1]));
            tmax1 = fmaxf(tmax1, fmaxf(s[j][2], s[j][3]));
        }
        tmax0 = fmaxf(tmax0, __shfl_xor_sync(0xffffffffu, tmax0, 1));
        tmax0 = fmaxf(tmax0, __shfl_xor_sync(0xffffffffu, tmax0, 2));
        tmax1 = fmaxf(tmax1, __shfl_xor_sync(0xffffffffu, tmax1, 1));
        tmax1 = fmaxf(tmax1, __shfl_xor_sync(0xffffffffu, tmax1, 2));

        float nm0 = fmaxf(mrow0, tmax0), nm1 = fmaxf(mrow1, tmax1);
        float corr0 = __expf(mrow0 - nm0), corr1 = __expf(mrow1 - nm1);
        mrow0 = nm0; mrow1 = nm1;
#pragma unroll
        for (int j = 0; j < 8; ++j) {
            oacc[j][0] *= corr0; oacc[j][1] *= corr0;
            oacc[j][2] *= corr1; oacc[j][3] *= corr1;
        }

        float ps0 = 0.0f, ps1 = 0.0f;
        uint32_t aH[4][4], aL[4][4];
#pragma unroll
        for (int j = 0; j < 8; ++j) {
            float p0 = __expf(s[j][0] - nm0), p1 = __expf(s[j][1] - nm0);
            float p2 = __expf(s[j][2] - nm1), p3 = __expf(s[j][3] - nm1);
            ps0 += p0 + p1; ps1 += p2 + p3;
            __nv_bfloat16 h0 = __float2bfloat16(p0), h1 = __float2bfloat16(p1);
            __nv_bfloat16 h2 = __float2bfloat16(p2), h3 = __float2bfloat16(p3);
            const int jp = j >> 1, sel = (j & 1) * 2;
            aH[jp][sel + 0] = pkbf2(__bfloat162float(h0), __bfloat162float(h1));
            aH[jp][sel + 1] = pkbf2(__bfloat162float(h2), __bfloat162float(h3));
            aL[jp][sel + 0] = pkbf2(p0 - __bfloat162float(h0), p1 - __bfloat162float(h1));
            aL[jp][sel + 1] = pkbf2(p2 - __bfloat162float(h2), p3 - __bfloat162float(h3));
        }
        ps0 += __shfl_xor_sync(0xffffffffu, ps0, 1);
        ps0 += __shfl_xor_sync(0xffffffffu, ps0, 2);
        ps1 += __shfl_xor_sync(0xffffffffu, ps1, 1);
        ps1 += __shfl_xor_sync(0xffffffffu, ps1, 2);
        lrow0 = lrow0 * corr0 + ps0;
        lrow1 = lrow1 * corr1 + ps1;

#pragma unroll
        for (int jd = 0; jd < 8; ++jd)
#pragma unroll
            for (int ks = 0; ks < 4; ++ks) {
                uint32_t vh2[2], vl2[2];
                uint32_t ad = ((16 * ks + (lane & 15)) * ASTR + 8 * jd) * 2;
                ldsm_x2t(vh2, vhb + ad);
                ldsm_x2t(vl2, vlb + ad);
                mma16816(oacc[jd], aH[ks], vh2);
                mma16816(oacc[jd], aH[ks], vl2);
                mma16816(oacc[jd], aL[ks], vh2);
            }
    }

    const float inv0 = 1.0f / lrow0, inv1 = 1.0f / lrow1;
    const int er = lane >> 2, ec = (lane & 3) * 2;
    const size_t r0o = (rowbase + q0 + wq + er) * NQKV + coff;
    const size_t r1o = r0o + (size_t)8 * NQKV;
#pragma unroll
    for (int jd = 0; jd < 8; ++jd) {
        const int n = 8 * jd + ec;
        float v0 = oacc[jd][0] * inv0, v1 = oacc[jd][1] * inv0;
        float v2 = oacc[jd][2] * inv1, v3 = oacc[jd][3] * inv1;
        __nv_bfloat16 h0 = __float2bfloat16(v0), h1 = __float2bfloat16(v1);
        __nv_bfloat16 h2 = __float2bfloat16(v2), h3 = __float2bfloat16(v3);
        *(__nv_bfloat162*)&AOh[r0o + n] = __halves2bfloat162(h0, h1);
        *(__nv_bfloat162*)&AOh[r1o + n] = __halves2bfloat162(h2, h3);
        __nv_bfloat16 l0 = __float2bfloat16(v0 - __bfloat162float(h0));
        __nv_bfloat16 l1 = __float2bfloat16(v1 - __bfloat162float(h1));
        __nv_bfloat16 l2 = __float2bfloat16(v2 - __bfloat162float(h2));
        __nv_bfloat16 l3 = __float2bfloat16(v3 - __bfloat162float(h3));
        *(__nv_bfloat162*)&AOl[r0o + n] = __halves2bfloat162(l0, l1);
        *(__nv_bfloat162*)&AOl[r1o + n] = __halves2bfloat162(l2, l3);
    }
}

// -------------------- launch ---------------------------------------------------
extern "C" void kernel_launch(void* const* d_in, const int* in_sizes, int n_in,
                              void* d_out, int out_size) {
    const float* x  = (const float*)d_in[0];
    const float* Wq = (const float*)d_in[1];
    const float* bq = (const float*)d_in[2];
    const float* Wk = (const float*)d_in[3];
    const float* bk = (const float*)d_in[4];
    const float* Wv = (const float*)d_in[5];
    const float* bv = (const float*)d_in[6];
    const float* Wo = (const float*)d_in[7];
    const float* bo = (const float*)d_in[8];
    float* out = (float*)d_out;

    __nv_bfloat16 *xh, *xl, *qb, *kb, *vh, *vl, *aoh, *aol;
    __nv_bfloat16 *wqh, *wql, *wkh, *wkl, *wvh, *wvl, *woh, *wol;
    cudaGetSymbolAddress((void**)&xh,  g_xh);  cudaGetSymbolAddress((void**)&xl,  g_xl);
    cudaGetSymbolAddress((void**)&qb,  g_qb);  cudaGetSymbolAddress((void**)&kb,  g_kb);
    cudaGetSymbolAddress((void**)&vh,  g_vh);  cudaGetSymbolAddress((void**)&vl,  g_vl);
    cudaGetSymbolAddress((void**)&aoh, g_aoh); cudaGetSymbolAddress((void**)&aol, g_aol);
    cudaGetSymbolAddress((void**)&wqh, g_wqh); cudaGetSymbolAddress((void**)&wql, g_wql);
    cudaGetSymbolAddress((void**)&wkh, g_wkh); cudaGetSymbolAddress((void**)&wkl, g_wkl);
    cudaGetSymbolAddress((void**)&wvh, g_wvh); cudaGetSymbolAddress((void**)&wvl, g_wvl);
    cudaGetSymbolAddress((void**)&woh, g_woh); cudaGetSymbolAddress((void**)&wol, g_wol);

    cudaFuncSetAttribute(gemm_bf16x3<0>, cudaFuncAttributeMaxDynamicSharedMemorySize, GSM_TOTAL);
    cudaFuncSetAttribute(gemm_bf16x3<1>, cudaFuncAttributeMaxDynamicSharedMemorySize, GSM_TOTAL);
    cudaFuncSetAttribute(gemm_bf16x3<2>, cudaFuncAttributeMaxDynamicSharedMemorySize, GSM_TOTAL);

    // 1) split x into bf16 hi/lo
    split_kernel<<<(NTOK * DMODEL / 2 + 255) / 256, 256>>>(x, xh, xl, NTOK * DMODEL / 2);

    // 2) transpose+split weights (QKV fused via grid.z; Wo separate shape)
    dim3 tb(32, 8);
    transpose_split3<<<dim3(NQKV / 32, DMODEL / 32, 3), tb>>>(
        Wq, wqh, wql, Wk, wkh, wkl, Wv, wvh, wvl, DMODEL, NQKV);
    transpose_split3<<<dim3(DMODEL / 32, NQKV / 32, 1), tb>>>(
        Wo, woh, wol, nullptr, nullptr, nullptr, nullptr, nullptr, nullptr, NQKV, DMODEL);

    // 3) QKV projections (HMMA): Q,K -> bf16; V -> bf16 hi/lo
    dim3 gq(NQKV / 128, NTOK / 256);
    gemm_bf16x3<1><<<gq, 512, GSM_TOTAL>>>(xh, xl, wqh, wql, bq, nullptr, qb, nullptr, DMODEL, NQKV);
    gemm_bf16x3<1><<<gq, 512, GSM_TOTAL>>>(xh, xl, wkh, wkl, bk, nullptr, kb, nullptr, DMODEL, NQKV);
    gemm_bf16x3<2><<<gq, 512, GSM_TOTAL>>>(xh, xl, wvh, wvl, bv, nullptr, vh, vl, DMODEL, NQKV);

    // 4) HMMA flash attention -> AO hi/lo directly
    dim3 ga(SEQ / 64, NHEAD, 8);
    attn_mma<<<ga, 128>>>(qb, kb, vh, vl, aoh, aol);

    // 5) output projection (fp32 out): [8192,512] @ [1024,512]^T + bo
    dim3 go(DMODEL / 128, NTOK / 256);
    gemm_bf16x3<0><<<go, 512, GSM_TOTAL>>>(aoh, aol, woh, wol, bo, out, nullptr, nullptr, NQKV, DMODEL);
}

// round 11
// speedup vs baseline: 1.2704x; 1.2704x over previous
#include <cuda_runtime.h>
#include <cuda_bf16.h>
#include <cstdint>

#define NTOK   8192     // 8 * 1024 tokens
#define DMODEL 1024
#define NQKV   512      // H * D_K
#define NCAT   1536     // Q|K|V concatenated
#define SEQ    1024
#define NHEAD  8
#define DHEAD  64

// -------------------- scratch (device globals: allocation-guard safe) ----------
__device__ __nv_bfloat16 g_xh[NTOK * DMODEL], g_xl[NTOK * DMODEL];
__device__ __nv_bfloat16 g_qkvh[NTOK * NCAT], g_qkvl[NTOK * NCAT];
__device__ __nv_bfloat16 g_aoh[NTOK * NQKV],  g_aol[NTOK * NQKV];
__device__ __nv_bfloat16 g_wch[NCAT * DMODEL], g_wcl[NCAT * DMODEL];
__device__ __nv_bfloat16 g_woh[DMODEL * NQKV], g_wol[DMODEL * NQKV];
__device__ float g_bcat[NCAT];

extern __shared__ unsigned char dynsmem[];

// -------------------- PTX helpers (base-target sm_80+ instructions) ------------
__device__ __forceinline__ uint32_t smem_to_u32(const void* p) {
    uint32_t a;
    asm("{ .reg .u64 t; cvta.to.shared.u64 t, %1; cvt.u32.u64 %0, t; }"
        : "=r"(a) : "l"(p));
    return a;
}
__device__ __forceinline__ void cp16(uint32_t dst, const void* src) {
    asm volatile("cp.async.ca.shared.global [%0], [%1], 16;"
                 :: "r"(dst), "l"(src) : "memory");
}
#define CP_COMMIT() asm volatile("cp.async.commit_group;" ::: "memory")
#define CP_WAIT1()  asm volatile("cp.async.wait_group 1;" ::: "memory")
#define CP_WAIT0()  asm volatile("cp.async.wait_group 0;" ::: "memory")

__device__ __forceinline__ void ldsm_x4(uint32_t* r, uint32_t addr) {
    asm volatile("ldmatrix.sync.aligned.m8n8.x4.shared.b16 {%0,%1,%2,%3}, [%4];"
                 : "=r"(r[0]), "=r"(r[1]), "=r"(r[2]), "=r"(r[3]) : "r"(addr));
}
__device__ __forceinline__ void ldsm_x2(uint32_t* r, uint32_t addr) {
    asm volatile("ldmatrix.sync.aligned.m8n8.x2.shared.b16 {%0,%1}, [%2];"
                 : "=r"(r[0]), "=r"(r[1]) : "r"(addr));
}
__device__ __forceinline__ void ldsm_x2t(uint32_t* r, uint32_t addr) {
    asm volatile("ldmatrix.sync.aligned.m8n8.x2.trans.shared.b16 {%0,%1}, [%2];"
                 : "=r"(r[0]), "=r"(r[1]) : "r"(addr));
}
__device__ __forceinline__ void mma16816(float* c, const uint32_t* a, const uint32_t* b) {
    asm volatile("mma.sync.aligned.m16n8k16.row.col.f32.bf16.bf16.f32 "
                 "{%0,%1,%2,%3}, {%4,%5,%6,%7}, {%8,%9}, {%0,%1,%2,%3};"
                 : "+f"(c[0]), "+f"(c[1]), "+f"(c[2]), "+f"(c[3])
                 : "r"(a[0]), "r"(a[1]), "r"(a[2]), "r"(a[3]),
                   "r"(b[0]), "r"(b[1]));
}
__device__ __forceinline__ uint32_t pkbf2(float lo, float hi) {
    __nv_bfloat162 t = __floats2bfloat162_rn(lo, hi);
    return reinterpret_cast<uint32_t&>(t);
}

// -------------------- pre-pass: split fp32 -> bf16 hi/lo -----------------------
__global__ void split_kernel(const float* __restrict__ src,
                             __nv_bfloat16* __restrict__ hi,
                             __nv_bfloat16* __restrict__ lo, int n2) {
    int i = blockIdx.x * blockDim.x + threadIdx.x;
    if (i < n2) {
        float2 v = ((const float2*)src)[i];
        __nv_bfloat16 h0 = __float2bfloat16(v.x);
        __nv_bfloat16 h1 = __float2bfloat16(v.y);
        __nv_bfloat16 l0 = __float2bfloat16(v.x - __bfloat162float(h0));
        __nv_bfloat16 l1 = __float2bfloat16(v.y - __bfloat162float(h1));
        ((__nv_bfloat162*)hi)[i] = __halves2bfloat162(h0, h1);
        ((__nv_bfloat162*)lo)[i] = __halves2bfloat162(l0, l1);
    }
}

// -------------------- pre-pass: bias concat ------------------------------------
__global__ void bias_cat(const float* __restrict__ bq, const float* __restrict__ bk,
                         const float* __restrict__ bv, float* __restrict__ bc) {
    int i = blockIdx.x * blockDim.x + threadIdx.x;
    if (i < NCAT)
        bc[i] = (i < 512) ? bq[i] : (i < 1024) ? bk[i - 512] : bv[i - 1024];
}

// -------------------- pre-pass: W[K,N] fp32 -> Wt[N,K] bf16 hi/lo --------------
__global__ void transpose_split3(const float* __restrict__ W0, __nv_bfloat16* __restrict__ T0h,
                                 __nv_bfloat16* __restrict__ T0l,
                                 const float* __restrict__ W1, __nv_bfloat16* __restrict__ T1h,
                                 __nv_bfloat16* __restrict__ T1l,
                                 const float* __restrict__ W2, __nv_bfloat16* __restrict__ T2h,
                                 __nv_bfloat16* __restrict__ T2l,
                                 int Kd, int Nd) {
    __shared__ float t[32][33];
    const float* W = (blockIdx.z == 0) ? W0 : (blockIdx.z == 1) ? W1 : W2;
    __nv_bfloat16* Th = (blockIdx.z == 0) ? T0h : (blockIdx.z == 1) ? T1h : T2h;
    __nv_bfloat16* Tl = (blockIdx.z == 0) ? T0l : (blockIdx.z == 1) ? T1l : T2l;
    int k0 = blockIdx.y * 32, n0 = blockIdx.x * 32;
    for (int i = threadIdx.y; i < 32; i += 8)
        t[i][threadIdx.x] = W[(size_t)(k0 + i) * Nd + n0 + threadIdx.x];
    __syncthreads();
    for (int i = threadIdx.y; i < 32; i += 8) {
        float v = t[threadIdx.x][i];
        __nv_bfloat16 h = __float2bfloat16(v);
        __nv_bfloat16 l = __float2bfloat16(v - __bfloat162float(h));
        size_t o = (size_t)(n0 + i) * Kd + k0 + threadIdx.x;
        Th[o] = h; Tl[o] = l;
    }
}

// -------------------- bf16x3 HMMA GEMM (R7 config): C = A @ B^T + bias ---------
// CTA tile 128x128, BK=32, 256 threads, 8 warps of 64x32, double-buffered.
// smem rows padded to 80 B (40 bf16): conflict-free ldmatrix.
// OM=0: fp32 out. OM=2: bf16 hi/lo out. OM=3: bf16 hi always, lo iff n>=1024.
#define GASTRIDE   40                       // bf16 elems per smem row
#define GMAT_BYTES (128 * GASTRIDE * 2)     // 10240 B per matrix tile
#define GSTAGE     (4 * GMAT_BYTES)         // Ah, Al, Bh, Bl = 40960 B
#define GSM_TOTAL  (2 * GSTAGE)             // double buffer = 81920 B

template <int OM>
__global__ __launch_bounds__(256)
void gemm_bf16x3(const __nv_bfloat16* __restrict__ Ah, const __nv_bfloat16* __restrict__ Al,
                 const __nv_bfloat16* __restrict__ Bh, const __nv_bfloat16* __restrict__ Bl,
                 const float* __restrict__ bias, float* __restrict__ Cf,
                 __nv_bfloat16* __restrict__ Ch, __nv_bfloat16* __restrict__ Cl,
                 int K, int N) {
    const uint32_t smem_base = smem_to_u32(dynsmem);
    const int tid  = threadIdx.x;
    const int wid  = tid >> 5, lane = tid & 31;
    const int m0 = blockIdx.y * 128, n0 = blockIdx.x * 128;

    // ---- loader mapping: 64 threads per matrix, 2 rows each, 4x16B per row ----
    const int mat = tid >> 6;           // 0=Ah 1=Al 2=Bh 3=Bl
    const int rr  = tid & 63;
    const __nv_bfloat16* mats[4] = { Ah, Al, Bh, Bl };
    const int brow = (mat < 2) ? m0 : n0;
    const __nv_bfloat16* gsrc = mats[mat] + (size_t)brow * K;
    const uint32_t sdst = smem_base + mat * GMAT_BYTES;

    // ---- compute mapping ------------------------------------------------------
    const int wm = (wid & 1) * 64;
    const int wn = (wid >> 1) * 32;
    const int aRowOff = lane & 15;
    const int aColOff = (lane & 16) ? 8 : 0;
    const int bRowOff = lane & 7;
    const int bColOff = (lane & 8) ? 8 : 0;

    float acc[4][4][4];
#pragma unroll
    for (int i = 0; i < 4; i++)
#pragma unroll
        for (int j = 0; j < 4; j++)
#pragma unroll
            for (int c = 0; c < 4; c++) acc[i][j][c] = 0.0f;

    const int nstage = K >> 5;
    {
#pragma unroll
        for (int h = 0; h < 2; ++h) {
            int row = rr + h * 64;
            const __nv_bfloat16* src = gsrc + (size_t)row * K;
            uint32_t d = sdst + row * (GASTRIDE * 2);
#pragma unroll
            for (int c = 0; c < 4; ++c) cp16(d + c * 16, src + c * 8);
        }
        CP_COMMIT();
    }

    for (int s = 0; s < nstage; ++s) {
        if (s + 1 < nstage) {
            const int k0 = (s + 1) << 5;
            const uint32_t boff = ((s + 1) & 1) * GSTAGE;
#pragma unroll
            for (int h = 0; h < 2; ++h) {
                int row = rr + h * 64;
                const __nv_bfloat16* src = gsrc + (size_t)row * K + k0;
                uint32_t d = sdst + boff + row * (GASTRIDE * 2);
#pragma unroll
                for (int c = 0; c < 4; ++c) cp16(d + c * 16, src + c * 8);
            }
            CP_COMMIT();
            CP_WAIT1();
        } else {
            CP_WAIT0();
        }
        __syncthreads();

        const uint32_t sb = smem_base + (s & 1) * GSTAGE;
        const uint32_t sbB = sb + 2 * GMAT_BYTES;
#pragma unroll
        for (int kc = 0; kc < 32; kc += 16) {
            uint32_t ah[4][4], al[4][4], bh[4][2], bl[4][2];
#pragma unroll
            for (int i = 0; i < 4; ++i) {
                uint32_t addr = sb + (wm + 16 * i + aRowOff) * (GASTRIDE * 2)
                                   + (kc + aColOff) * 2;
                ldsm_x4(ah[i], addr);
                ldsm_x4(al[i], addr + GMAT_BYTES);
            }
#pragma unroll
            for (int j = 0; j < 4; ++j) {
                uint32_t addr = sbB + (wn + 8 * j + bRowOff) * (GASTRIDE * 2)
                                    + (kc + bColOff) * 2;
                ldsm_x2(bh[j], addr);
                ldsm_x2(bl[j], addr + GMAT_BYTES);
            }
#pragma unroll
            for (int i = 0; i < 4; ++i)
#pragma unroll
                for (int j = 0; j < 4; ++j) {
                    mma16816(acc[i][j], ah[i], bh[j]);
                    mma16816(acc[i][j], ah[i], bl[j]);
                    mma16816(acc[i][j], al[i], bh[j]);
                }
        }
        __syncthreads();
    }

    // ---- epilogue ----
    const int er = lane >> 2;
    const int ec = (lane & 3) * 2;
#pragma unroll
    for (int j = 0; j < 4; ++j) {
        const int n = n0 + wn + 8 * j + ec;
        const float b0 = bias[n], b1 = bias[n + 1];
#pragma unroll
        for (int i = 0; i < 4; ++i) {
            const int m = m0 + wm + 16 * i + er;
            float v0 = acc[i][j][0] + b0, v1 = acc[i][j][1] + b1;
            float v2 = acc[i][j][2] + b0, v3 = acc[i][j][3] + b1;
            if (OM == 0) {
                *(float2*)(Cf + (size_t)m * N + n)       = make_float2(v0, v1);
                *(float2*)(Cf + (size_t)(m + 8) * N + n) = make_float2(v2, v3);
            } else {
                __nv_bfloat16 h0 = __float2bfloat16(v0), h1 = __float2bfloat16(v1);
                __nv_bfloat16 h2 = __float2bfloat16(v2), h3 = __float2bfloat16(v3);
                *(__nv_bfloat162*)(Ch + (size_t)m * N + n) = __halves2bfloat162(h0, h1);
                *(__nv_bfloat162*)(Ch + (size_t)(m + 8) * N + n) = __halves2bfloat162(h2, h3);
                if (OM == 2 || (OM == 3 && n >= 1024)) {
                    __nv_bfloat16 l0 = __float2bfloat16(v0 - __bfloat162float(h0));
                    __nv_bfloat16 l1 = __float2bfloat16(v1 - __bfloat162float(h1));
                    __nv_bfloat16 l2 = __float2bfloat16(v2 - __bfloat162float(h2));
                    __nv_bfloat16 l3 = __float2bfloat16(v3 - __bfloat162float(h3));
                    *(__nv_bfloat162*)(Cl + (size_t)m * N + n) = __halves2bfloat162(l0, l1);
                    *(__nv_bfloat162*)(Cl + (size_t)(m + 8) * N + n) = __halves2bfloat162(l2, l3);
                }
            }
        }
    }
}

// -------------------- HMMA flash attention (validated R7; stride = NCAT) -------
#define ASTR 72   // bf16 per smem row

__global__ __launch_bounds__(128)
void attn_mma(const __nv_bfloat16* __restrict__ QKVh, const __nv_bfloat16* __restrict__ QKVl,
              __nv_bfloat16* __restrict__ AOh, __nv_bfloat16* __restrict__ AOl) {
    __shared__ __align__(16) __nv_bfloat16 Qs[64 * ASTR];
    __shared__ __align__(16) __nv_bfloat16 Ks[64 * ASTR];
    __shared__ __align__(16) __nv_bfloat16 Vhs[64 * ASTR];
    __shared__ __align__(16) __nv_bfloat16 Vls[64 * ASTR];

    const int tid = threadIdx.x, wid = tid >> 5, lane = tid & 31;
    const int q0 = blockIdx.x * 64, h = blockIdx.y, b = blockIdx.z;
    const size_t rowbase = (size_t)b * SEQ;
    const int coff = h * DHEAD;

    const __nv_bfloat16* Qp  = QKVh + coff;            // Q cols [0,512)
    const __nv_bfloat16* Kp  = QKVh + 512 + coff;      // K cols [512,1024)
    const __nv_bfloat16* Vhp = QKVh + 1024 + coff;     // V cols [1024,1536)
    const __nv_bfloat16* Vlp = QKVl + 1024 + coff;

    const int lr = tid >> 1, lc = (tid & 1) * 32;
    {
        const __nv_bfloat16* src = Qp + (rowbase + q0 + lr) * NCAT + lc;
#pragma unroll
        for (int c = 0; c < 4; ++c)
            *(uint4*)&Qs[lr * ASTR + lc + 8 * c] = *(const uint4*)(src + 8 * c);
    }
    __syncthreads();

    const uint32_t qbase = smem_to_u32(Qs), kbase = smem_to_u32(Ks);
    const uint32_t vhb = smem_to_u32(Vhs), vlb = smem_to_u32(Vls);
    const int wq = wid * 16;

    uint32_t qf[4][4];
#pragma unroll
    for (int ks = 0; ks < 4; ++ks)
        ldsm_x4(qf[ks], qbase + ((wq + (lane & 15)) * ASTR + ks * 16
                                 + ((lane & 16) ? 8 : 0)) * 2);

    float oacc[8][4];
#pragma unroll
    for (int j = 0; j < 8; ++j)
#pragma unroll
        for (int c = 0; c < 4; ++c) oacc[j][c] = 0.0f;
    float mrow0 = -1e30f, mrow1 = -1e30f, lrow0 = 0.0f, lrow1 = 0.0f;

    for (int kv0 = 0; kv0 < SEQ; kv0 += 64) {
        __syncthreads();
        {
            const size_t grow = (rowbase + kv0 + lr) * NCAT + lc;
            const int so = lr * ASTR + lc;
#pragma unroll
            for (int c = 0; c < 4; ++c) {
                *(uint4*)&Ks[so + 8 * c]  = *(const uint4*)(Kp  + grow + 8 * c);
                *(uint4*)&Vhs[so + 8 * c] = *(const uint4*)(Vhp + grow + 8 * c);
                *(uint4*)&Vls[so + 8 * c] = *(const uint4*)(Vlp + grow + 8 * c);
            }
        }
        __syncthreads();

        float s[8][4];
#pragma unroll
        for (int j = 0; j < 8; ++j)
#pragma unroll
            for (int c = 0; c < 4; ++c) s[j][c] = 0.0f;
#pragma unroll
        for (int ks = 0; ks < 4; ++ks)
#pragma unroll
            for (int j = 0; j < 8; ++j) {
                uint32_t kf[2];
                ldsm_x2(kf, kbase + ((8 * j + (lane & 7)) * ASTR + ks * 16
                                     + ((lane & 8) ? 8 : 0)) * 2);
                mma16816(s[j], qf[ks], kf);
            }

        float tmax0 = -1e30f, tmax1 = -1e30f;
#pragma unroll
        for (int j = 0; j < 8; ++j) {
            s[j][0] *= 0.125f; s[j][1] *= 0.125f; s[j][2] *= 0.125f; s[j][3] *= 0.125f;
            tmax0 = fmaxf(tmax0, fmaxf(s[j][0], s[j][1]));
            tmax1 = fmaxf(tmax1, fmaxf(s[j][2], s[j][3]));
        }
        tmax0 = fmaxf(tmax0, __shfl_xor_sync(0xffffffffu, tmax0, 1));
        tmax0 = fmaxf(tmax0, __shfl_xor_sync(0xffffffffu, tmax0, 2));
        tmax1 = fmaxf(tmax1, __shfl_xor_sync(0xffffffffu, tmax1, 1));
        tmax1 = fmaxf(tmax1, __shfl_xor_sync(0xffffffffu, tmax1, 2));

        float nm0 = fmaxf(mrow0, tmax0), nm1 = fmaxf(mrow1, tmax1);
        float corr0 = __expf(mrow0 - nm0), corr1 = __expf(mrow1 - nm1);
        mrow0 = nm0; mrow1 = nm1;
#pragma unroll
        for (int j = 0; j < 8; ++j) {
            oacc[j][0] *= corr0; oacc[j][1] *= corr0;
            oacc[j][2] *= corr1; oacc[j][3] *= corr1;
        }

        float ps0 = 0.0f, ps1 = 0.0f;
        uint32_t aH[4][4], aL[4][4];
#pragma unroll
        for (int j = 0; j < 8; ++j) {
            float p0 = __expf(s[j][0] - nm0), p1 = __expf(s[j][1] - nm0);
            float p2 = __expf(s[j][2] - nm1), p3 = __expf(s[j][3] - nm1);
            ps0 += p0 + p1; ps1 += p2 + p3;
            __nv_bfloat16 h0 = __float2bfloat16(p0), h1 = __float2bfloat16(p1);
            __nv_bfloat16 h2 = __float2bfloat16(p2), h3 = __float2bfloat16(p3);
            const int jp = j >> 1, sel = (j & 1) * 2;
            aH[jp][sel + 0] = pkbf2(__bfloat162float(h0), __bfloat162float(h1));
            aH[jp][sel + 1] = pkbf2(__bfloat162float(h2), __bfloat162float(h3));
            aL[jp][sel + 0] = pkbf2(p0 - __bfloat162float(h0), p1 - __bfloat162float(h1));
            aL[jp][sel + 1] = pkbf2(p2 - __bfloat162float(h2), p3 - __bfloat162float(h3));
        }
        ps0 += __shfl_xor_sync(0xffffffffu, ps0, 1);
        ps0 += __shfl_xor_sync(0xffffffffu, ps0, 2);
        ps1 += __shfl_xor_sync(0xffffffffu, ps1, 1);
        ps1 += __shfl_xor_sync(0xffffffffu, ps1, 2);
        lrow0 = lrow0 * corr0 + ps0;
        lrow1 = lrow1 * corr1 + ps1;

#pragma unroll
        for (int jd = 0; jd < 8; ++jd)
#pragma unroll
            for (int ks = 0; ks < 4; ++ks) {
                uint32_t vh2[2], vl2[2];
                uint32_t ad = ((16 * ks + (lane & 15)) * ASTR + 8 * jd) * 2;
                ldsm_x2t(vh2, vhb + ad);
                ldsm_x2t(vl2, vlb + ad);
                mma16816(oacc[jd], aH[ks], vh2);
                mma16816(oacc[jd], aH[ks], vl2);
                mma16816(oacc[jd], aL[ks], vh2);
            }
    }

    const float inv0 = 1.0f / lrow0, inv1 = 1.0f / lrow1;
    const int er = lane >> 2, ec = (lane & 3) * 2;
    const size_t r0o = (rowbase + q0 + wq + er) * NQKV + coff;
    const size_t r1o = r0o + (size_t)8 * NQKV;
#pragma unroll
    for (int jd = 0; jd < 8; ++jd) {
        const int n = 8 * jd + ec;
        float v0 = oacc[jd][0] * inv0, v1 = oacc[jd][1] * inv0;
        float v2 = oacc[jd][2] * inv1, v3 = oacc[jd][3] * inv1;
        __nv_bfloat16 h0 = __float2bfloat16(v0), h1 = __float2bfloat16(v1);
        __nv_bfloat16 h2 = __float2bfloat16(v2), h3 = __float2bfloat16(v3);
        *(__nv_bfloat162*)&AOh[r0o + n] = __halves2bfloat162(h0, h1);
        *(__nv_bfloat162*)&AOh[r1o + n] = __halves2bfloat162(h2, h3);
        __nv_bfloat16 l0 = __float2bfloat16(v0 - __bfloat162float(h0));
        __nv_bfloat16 l1 = __float2bfloat16(v1 - __bfloat162float(h1));
        __nv_bfloat16 l2 = __float2bfloat16(v2 - __bfloat162float(h2));
        __nv_bfloat16 l3 = __float2bfloat16(v3 - __bfloat162float(h3));
        *(__nv_bfloat162*)&AOl[r0o + n] = __halves2bfloat162(l0, l1);
        *(__nv_bfloat162*)&AOl[r1o + n] = __halves2bfloat162(l2, l3);
    }
}

// -------------------- launch ---------------------------------------------------
extern "C" void kernel_launch(void* const* d_in, const int* in_sizes, int n_in,
                              void* d_out, int out_size) {
    const float* x  = (const float*)d_in[0];
    const float* Wq = (const float*)d_in[1];
    const float* bq = (const float*)d_in[2];
    const float* Wk = (const float*)d_in[3];
    const float* bk = (const float*)d_in[4];
    const float* Wv = (const float*)d_in[5];
    const float* bv = (const float*)d_in[6];
    const float* Wo = (const float*)d_in[7];
    const float* bo = (const float*)d_in[8];
    float* out = (float*)d_out;

    __nv_bfloat16 *xh, *xl, *qkvh, *qkvl, *aoh, *aol, *wch, *wcl, *woh, *wol;
    float* bcat;
    cudaGetSymbolAddress((void**)&xh,   g_xh);   cudaGetSymbolAddress((void**)&xl,   g_xl);
    cudaGetSymbolAddress((void**)&qkvh, g_qkvh); cudaGetSymbolAddress((void**)&qkvl, g_qkvl);
    cudaGetSymbolAddress((void**)&aoh,  g_aoh);  cudaGetSymbolAddress((void**)&aol,  g_aol);
    cudaGetSymbolAddress((void**)&wch,  g_wch);  cudaGetSymbolAddress((void**)&wcl,  g_wcl);
    cudaGetSymbolAddress((void**)&woh,  g_woh);  cudaGetSymbolAddress((void**)&wol,  g_wol);
    cudaGetSymbolAddress((void**)&bcat, g_bcat);

    cudaFuncSetAttribute(gemm_bf16x3<0>, cudaFuncAttributeMaxDynamicSharedMemorySize, GSM_TOTAL);
    cudaFuncSetAttribute(gemm_bf16x3<3>, cudaFuncAttributeMaxDynamicSharedMemorySize, GSM_TOTAL);

    // 1) split x into bf16 hi/lo; bias concat
    split_kernel<<<(NTOK * DMODEL / 2 + 255) / 256, 256>>>(x, xh, xl, NTOK * DMODEL / 2);
    bias_cat<<<(NCAT + 255) / 256, 256>>>(bq, bk, bv, bcat);

    // 2) transpose+split weights into concatenated buffer (Q rows 0-511,
    //    K rows 512-1023, V rows 1024-1535); Wo separately.
    dim3 tb(32, 8);
    transpose_split3<<<dim3(NQKV / 32, DMODEL / 32, 3), tb>>>(
        Wq, wch, wcl,
        Wk, wch + (size_t)512 * DMODEL,  wcl + (size_t)512 * DMODEL,
        Wv, wch + (size_t)1024 * DMODEL, wcl + (size_t)1024 * DMODEL,
        DMODEL, NQKV);
    transpose_split3<<<dim3(DMODEL / 32, NQKV / 32, 1), tb>>>(
        Wo, woh, wol, nullptr, nullptr, nullptr, nullptr, nullptr, nullptr, NQKV, DMODEL);

    // 3) fused QKV projection: [8192,1024] @ [1536,1024]^T -> qkv (hi; lo for V)
    dim3 gq(NCAT / 128, NTOK / 128);
    gemm_bf16x3<3><<<gq, 256, GSM_TOTAL>>>(xh, xl, wch, wcl, bcat,
                                           nullptr, qkvh, qkvl, DMODEL, NCAT);

    // 4) HMMA flash attention -> AO hi/lo
    dim3 ga(SEQ / 64, NHEAD, 8);
    attn_mma<<<ga, 128>>>(qkvh, qkvl, aoh, aol);

    // 5) output projection (fp32 out): [8192,512] @ [1024,512]^T + bo
    dim3 go(DMODEL / 128, NTOK / 128);
    gemm_bf16x3<0><<<go, 256, GSM_TOTAL>>>(aoh, aol, woh, wol, bo, out,
                                           nullptr, nullptr, NQKV, DMODEL);
}

// round 13
// speedup vs baseline: 1.4481x; 1.1399x over previous
#include <cuda_runtime.h>
#include <cuda_bf16.h>
#include <cstdint>

#define NTOK   8192     // 8 * 1024 tokens
#define DMODEL 1024
#define NQKV   512      // H * D_K
#define NCAT   1536     // Q|K|V concatenated
#define SEQ    1024
#define NHEAD  8
#define DHEAD  64

// -------------------- scratch (device globals: allocation-guard safe) ----------
__device__ __nv_bfloat16 g_xh[NTOK * DMODEL], g_xl[NTOK * DMODEL];
__device__ __nv_bfloat16 g_qkvh[NTOK * NCAT], g_qkvl[NTOK * NCAT];
__device__ __nv_bfloat16 g_aoh[NTOK * NQKV],  g_aol[NTOK * NQKV];
__device__ __nv_bfloat16 g_wch[NCAT * DMODEL], g_wcl[NCAT * DMODEL];
__device__ __nv_bfloat16 g_woh[DMODEL * NQKV], g_wol[DMODEL * NQKV];
__device__ float g_bcat[NCAT];

extern __shared__ unsigned char dynsmem[];

// -------------------- PTX helpers (base-target sm_80+ instructions) ------------
__device__ __forceinline__ uint32_t smem_to_u32(const void* p) {
    uint32_t a;
    asm("{ .reg .u64 t; cvta.to.shared.u64 t, %1; cvt.u32.u64 %0, t; }"
        : "=r"(a) : "l"(p));
    return a;
}
__device__ __forceinline__ void cp16(uint32_t dst, const void* src) {
    asm volatile("cp.async.ca.shared.global [%0], [%1], 16;"
                 :: "r"(dst), "l"(src) : "memory");
}
#define CP_COMMIT() asm volatile("cp.async.commit_group;" ::: "memory")
#define CP_WAIT1()  asm volatile("cp.async.wait_group 1;" ::: "memory")
#define CP_WAIT0()  asm volatile("cp.async.wait_group 0;" ::: "memory")

__device__ __forceinline__ void ldsm_x4(uint32_t* r, uint32_t addr) {
    asm volatile("ldmatrix.sync.aligned.m8n8.x4.shared.b16 {%0,%1,%2,%3}, [%4];"
                 : "=r"(r[0]), "=r"(r[1]), "=r"(r[2]), "=r"(r[3]) : "r"(addr));
}
__device__ __forceinline__ void ldsm_x2(uint32_t* r, uint32_t addr) {
    asm volatile("ldmatrix.sync.aligned.m8n8.x2.shared.b16 {%0,%1}, [%2];"
                 : "=r"(r[0]), "=r"(r[1]) : "r"(addr));
}
__device__ __forceinline__ void ldsm_x2t(uint32_t* r, uint32_t addr) {
    asm volatile("ldmatrix.sync.aligned.m8n8.x2.trans.shared.b16 {%0,%1}, [%2];"
                 : "=r"(r[0]), "=r"(r[1]) : "r"(addr));
}
__device__ __forceinline__ void mma16816(float* c, const uint32_t* a, const uint32_t* b) {
    asm volatile("mma.sync.aligned.m16n8k16.row.col.f32.bf16.bf16.f32 "
                 "{%0,%1,%2,%3}, {%4,%5,%6,%7}, {%8,%9}, {%0,%1,%2,%3};"
                 : "+f"(c[0]), "+f"(c[1]), "+f"(c[2]), "+f"(c[3])
                 : "r"(a[0]), "r"(a[1]), "r"(a[2]), "r"(a[3]),
                   "r"(b[0]), "r"(b[1]));
}
__device__ __forceinline__ uint32_t pkbf2(float lo, float hi) {
    __nv_bfloat162 t = __floats2bfloat162_rn(lo, hi);
    return reinterpret_cast<uint32_t&>(t);
}

// -------------------- pre-pass: split fp32 -> bf16 hi/lo -----------------------
__global__ void split_kernel(const float* __restrict__ src,
                             __nv_bfloat16* __restrict__ hi,
                             __nv_bfloat16* __restrict__ lo, int n2) {
    int i = blockIdx.x * blockDim.x + threadIdx.x;
    if (i < n2) {
        float2 v = ((const float2*)src)[i];
        __nv_bfloat16 h0 = __float2bfloat16(v.x);
        __nv_bfloat16 h1 = __float2bfloat16(v.y);
        __nv_bfloat16 l0 = __float2bfloat16(v.x - __bfloat162float(h0));
        __nv_bfloat16 l1 = __float2bfloat16(v.y - __bfloat162float(h1));
        ((__nv_bfloat162*)hi)[i] = __halves2bfloat162(h0, h1);
        ((__nv_bfloat162*)lo)[i] = __halves2bfloat162(l0, l1);
    }
}

// -------------------- pre-pass: bias concat ------------------------------------
__global__ void bias_cat(const float* __restrict__ bq, const float* __restrict__ bk,
                         const float* __restrict__ bv, float* __restrict__ bc) {
    int i = blockIdx.x * blockDim.x + threadIdx.x;
    if (i < NCAT)
        bc[i] = (i < 512) ? bq[i] : (i < 1024) ? bk[i - 512] : bv[i - 1024];
}

// -------------------- pre-pass: W[K,N] fp32 -> Wt[N,K] bf16 hi/lo --------------
__global__ void transpose_split3(const float* __restrict__ W0, __nv_bfloat16* __restrict__ T0h,
                                 __nv_bfloat16* __restrict__ T0l,
                                 const float* __restrict__ W1, __nv_bfloat16* __restrict__ T1h,
                                 __nv_bfloat16* __restrict__ T1l,
                                 const float* __restrict__ W2, __nv_bfloat16* __restrict__ T2h,
                                 __nv_bfloat16* __restrict__ T2l,
                                 int Kd, int Nd) {
    __shared__ float t[32][33];
    const float* W = (blockIdx.z == 0) ? W0 : (blockIdx.z == 1) ? W1 : W2;
    __nv_bfloat16* Th = (blockIdx.z == 0) ? T0h : (blockIdx.z == 1) ? T1h : T2h;
    __nv_bfloat16* Tl = (blockIdx.z == 0) ? T0l : (blockIdx.z == 1) ? T1l : T2l;
    int k0 = blockIdx.y * 32, n0 = blockIdx.x * 32;
    for (int i = threadIdx.y; i < 32; i += 8)
        t[i][threadIdx.x] = W[(size_t)(k0 + i) * Nd + n0 + threadIdx.x];
    __syncthreads();
    for (int i = threadIdx.y; i < 32; i += 8) {
        float v = t[threadIdx.x][i];
        __nv_bfloat16 h = __float2bfloat16(v);
        __nv_bfloat16 l = __float2bfloat16(v - __bfloat162float(h));
        size_t o = (size_t)(n0 + i) * Kd + k0 + threadIdx.x;
        Th[o] = h; Tl[o] = l;
    }
}

// -------------------- mixed-precision HMMA GEMM: C = A @ B^T + bias ------------
// CTA tile 128x128, BK=32, 256 threads, 8 warps of 64x32, double-buffered.
// smem rows padded to 80 B (40 bf16): conflict-free ldmatrix.
// OM=0: fp32 out, always bf16x3 (3 products).
// OM=3: fused QKV — tiles with n0<1024 (Q,K cols) use 1 product (plain bf16,
//       skips Al/Bl loads); tiles with n0>=1024 (V cols) use 3 products and
//       emit bf16 hi/lo. Precision: Q/K errors are attenuated through softmax
//       (validated R7: bf16-rounding Q,K moved final rel_err by <4e-6).
#define GASTRIDE   40                       // bf16 elems per smem row
#define GMAT_BYTES (128 * GASTRIDE * 2)     // 10240 B per matrix tile
#define GSTAGE     (4 * GMAT_BYTES)         // Ah, Al, Bh, Bl = 40960 B
#define GSM_TOTAL  (2 * GSTAGE)             // double buffer = 81920 B

template <int OM>
__global__ __launch_bounds__(256)
void gemm_bf16x3(const __nv_bfloat16* __restrict__ Ah, const __nv_bfloat16* __restrict__ Al,
                 const __nv_bfloat16* __restrict__ Bh, const __nv_bfloat16* __restrict__ Bl,
                 const float* __restrict__ bias, float* __restrict__ Cf,
                 __nv_bfloat16* __restrict__ Ch, __nv_bfloat16* __restrict__ Cl,
                 int K, int N) {
    const uint32_t smem_base = smem_to_u32(dynsmem);
    const int tid  = threadIdx.x;
    const int wid  = tid >> 5, lane = tid & 31;
    const int m0 = blockIdx.y * 128, n0 = blockIdx.x * 128;
    const bool fullp = (OM != 3) || (n0 >= 1024);   // 3-product vs 1-product tile

    // ---- loader mapping: 64 threads per matrix, 2 rows each, 4x16B per row ----
    const int mat = tid >> 6;           // 0=Ah 1=Al 2=Bh 3=Bl
    const int rr  = tid & 63;
    const __nv_bfloat16* mats[4] = { Ah, Al, Bh, Bl };
    const int brow = (mat < 2) ? m0 : n0;
    const __nv_bfloat16* gsrc = mats[mat] + (size_t)brow * K;
    const uint32_t sdst = smem_base + mat * GMAT_BYTES;
    const bool ldme = fullp || mat == 0 || mat == 2;   // skip Al/Bl on 1-product tiles

    // ---- compute mapping ------------------------------------------------------
    const int wm = (wid & 1) * 64;
    const int wn = (wid >> 1) * 32;
    const int aRowOff = lane & 15;
    const int aColOff = (lane & 16) ? 8 : 0;
    const int bRowOff = lane & 7;
    const int bColOff = (lane & 8) ? 8 : 0;

    float acc[4][4][4];
#pragma unroll
    for (int i = 0; i < 4; i++)
#pragma unroll
        for (int j = 0; j < 4; j++)
#pragma unroll
            for (int c = 0; c < 4; c++) acc[i][j][c] = 0.0f;

    const int nstage = K >> 5;
    if (ldme) {
#pragma unroll
        for (int h = 0; h < 2; ++h) {
            int row = rr + h * 64;
            const __nv_bfloat16* src = gsrc + (size_t)row * K;
            uint32_t d = sdst + row * (GASTRIDE * 2);
#pragma unroll
            for (int c = 0; c < 4; ++c) cp16(d + c * 16, src + c * 8);
        }
    }
    CP_COMMIT();

    for (int s = 0; s < nstage; ++s) {
        if (s + 1 < nstage) {
            const int k0 = (s + 1) << 5;
            const uint32_t boff = ((s + 1) & 1) * GSTAGE;
            if (ldme) {
#pragma unroll
                for (int h = 0; h < 2; ++h) {
                    int row = rr + h * 64;
                    const __nv_bfloat16* src = gsrc + (size_t)row * K + k0;
                    uint32_t d = sdst + boff + row * (GASTRIDE * 2);
#pragma unroll
                    for (int c = 0; c < 4; ++c) cp16(d + c * 16, src + c * 8);
                }
            }
            CP_COMMIT();
            CP_WAIT1();
        } else {
            CP_WAIT0();
        }
        __syncthreads();

        const uint32_t sb = smem_base + (s & 1) * GSTAGE;
        const uint32_t sbB = sb + 2 * GMAT_BYTES;
        if (fullp) {
#pragma unroll
            for (int kc = 0; kc < 32; kc += 16) {
                uint32_t ah[4][4], al[4][4], bh[4][2], bl[4][2];
#pragma unroll
                for (int i = 0; i < 4; ++i) {
                    uint32_t addr = sb + (wm + 16 * i + aRowOff) * (GASTRIDE * 2)
                                       + (kc + aColOff) * 2;
                    ldsm_x4(ah[i], addr);
                    ldsm_x4(al[i], addr + GMAT_BYTES);
                }
#pragma unroll
                for (int j = 0; j < 4; ++j) {
                    uint32_t addr = sbB + (wn + 8 * j + bRowOff) * (GASTRIDE * 2)
                                        + (kc + bColOff) * 2;
                    ldsm_x2(bh[j], addr);
                    ldsm_x2(bl[j], addr + GMAT_BYTES);
                }
#pragma unroll
                for (int i = 0; i < 4; ++i)
#pragma unroll
                    for (int j = 0; j < 4; ++j) {
                        mma16816(acc[i][j], ah[i], bh[j]);
                        mma16816(acc[i][j], ah[i], bl[j]);
                        mma16816(acc[i][j], al[i], bh[j]);
                    }
            }
        } else {
#pragma unroll
            for (int kc = 0; kc < 32; kc += 16) {
                uint32_t ah[4][4], bh[4][2];
#pragma unroll
                for (int i = 0; i < 4; ++i)
                    ldsm_x4(ah[i], sb + (wm + 16 * i + aRowOff) * (GASTRIDE * 2)
                                      + (kc + aColOff) * 2);
#pragma unroll
                for (int j = 0; j < 4; ++j)
                    ldsm_x2(bh[j], sbB + (wn + 8 * j + bRowOff) * (GASTRIDE * 2)
                                       + (kc + bColOff) * 2);
#pragma unroll
                for (int i = 0; i < 4; ++i)
#pragma unroll
                    for (int j = 0; j < 4; ++j)
                        mma16816(acc[i][j], ah[i], bh[j]);
            }
        }
        __syncthreads();
    }

    // ---- epilogue ----
    const int er = lane >> 2;
    const int ec = (lane & 3) * 2;
#pragma unroll
    for (int j = 0; j < 4; ++j) {
        const int n = n0 + wn + 8 * j + ec;
        const float b0 = bias[n], b1 = bias[n + 1];
#pragma unroll
        for (int i = 0; i < 4; ++i) {
            const int m = m0 + wm + 16 * i + er;
            float v0 = acc[i][j][0] + b0, v1 = acc[i][j][1] + b1;
            float v2 = acc[i][j][2] + b0, v3 = acc[i][j][3] + b1;
            if (OM == 0) {
                *(float2*)(Cf + (size_t)m * N + n)       = make_float2(v0, v1);
                *(float2*)(Cf + (size_t)(m + 8) * N + n) = make_float2(v2, v3);
            } else {
                __nv_bfloat16 h0 = __float2bfloat16(v0), h1 = __float2bfloat16(v1);
                __nv_bfloat16 h2 = __float2bfloat16(v2), h3 = __float2bfloat16(v3);
                *(__nv_bfloat162*)(Ch + (size_t)m * N + n) = __halves2bfloat162(h0, h1);
                *(__nv_bfloat162*)(Ch + (size_t)(m + 8) * N + n) = __halves2bfloat162(h2, h3);
                if (OM == 3 && n >= 1024) {
                    __nv_bfloat16 l0 = __float2bfloat16(v0 - __bfloat162float(h0));
                    __nv_bfloat16 l1 = __float2bfloat16(v1 - __bfloat162float(h1));
                    __nv_bfloat16 l2 = __float2bfloat16(v2 - __bfloat162float(h2));
                    __nv_bfloat16 l3 = __float2bfloat16(v3 - __bfloat162float(h3));
                    *(__nv_bfloat162*)(Cl + (size_t)m * N + n) = __halves2bfloat162(l0, l1);
                    *(__nv_bfloat162*)(Cl + (size_t)(m + 8) * N + n) = __halves2bfloat162(l2, l3);
                }
            }
        }
    }
}

// -------------------- HMMA flash attention (validated R7; stride = NCAT) -------
#define ASTR 72   // bf16 per smem row

__global__ __launch_bounds__(128)
void attn_mma(const __nv_bfloat16* __restrict__ QKVh, const __nv_bfloat16* __restrict__ QKVl,
              __nv_bfloat16* __restrict__ AOh, __nv_bfloat16* __restrict__ AOl) {
    __shared__ __align__(16) __nv_bfloat16 Qs[64 * ASTR];
    __shared__ __align__(16) __nv_bfloat16 Ks[64 * ASTR];
    __shared__ __align__(16) __nv_bfloat16 Vhs[64 * ASTR];
    __shared__ __align__(16) __nv_bfloat16 Vls[64 * ASTR];

    const int tid = threadIdx.x, wid = tid >> 5, lane = tid & 31;
    const int q0 = blockIdx.x * 64, h = blockIdx.y, b = blockIdx.z;
    const size_t rowbase = (size_t)b * SEQ;
    const int coff = h * DHEAD;

    const __nv_bfloat16* Qp  = QKVh + coff;            // Q cols [0,512)
    const __nv_bfloat16* Kp  = QKVh + 512 + coff;      // K cols [512,1024)
    const __nv_bfloat16* Vhp = QKVh + 1024 + coff;     // V cols [1024,1536)
    const __nv_bfloat16* Vlp = QKVl + 1024 + coff;

    const int lr = tid >> 1, lc = (tid & 1) * 32;
    {
        const __nv_bfloat16* src = Qp + (rowbase + q0 + lr) * NCAT + lc;
#pragma unroll
        for (int c = 0; c < 4; ++c)
            *(uint4*)&Qs[lr * ASTR + lc + 8 * c] = *(const uint4*)(src + 8 * c);
    }
    __syncthreads();

    const uint32_t qbase = smem_to_u32(Qs), kbase = smem_to_u32(Ks);
    const uint32_t vhb = smem_to_u32(Vhs), vlb = smem_to_u32(Vls);
    const int wq = wid * 16;

    uint32_t qf[4][4];
#pragma unroll
    for (int ks = 0; ks < 4; ++ks)
        ldsm_x4(qf[ks], qbase + ((wq + (lane & 15)) * ASTR + ks * 16
                                 + ((lane & 16) ? 8 : 0)) * 2);

    float oacc[8][4];
#pragma unroll
    for (int j = 0; j < 8; ++j)
#pragma unroll
        for (int c = 0; c < 4; ++c) oacc[j][c] = 0.0f;
    float mrow0 = -1e30f, mrow1 = -1e30f, lrow0 = 0.0f, lrow1 = 0.0f;

    for (int kv0 = 0; kv0 < SEQ; kv0 += 64) {
        __syncthreads();
        {
            const size_t grow = (rowbase + kv0 + lr) * NCAT + lc;
            const int so = lr * ASTR + lc;
#pragma unroll
            for (int c = 0; c < 4; ++c) {
                *(uint4*)&Ks[so + 8 * c]  = *(const uint4*)(Kp  + grow + 8 * c);
                *(uint4*)&Vhs[so + 8 * c] = *(const uint4*)(Vhp + grow + 8 * c);
                *(uint4*)&Vls[so + 8 * c] = *(const uint4*)(Vlp + grow + 8 * c);
            }
        }
        __syncthreads();

        float s[8][4];
#pragma unroll
        for (int j = 0; j < 8; ++j)
#pragma unroll
            for (int c = 0; c < 4; ++c) s[j][c] = 0.0f;
#pragma unroll
        for (int ks = 0; ks < 4; ++ks)
#pragma unroll
            for (int j = 0; j < 8; ++j) {
                uint32_t kf[2];
                ldsm_x2(kf, kbase + ((8 * j + (lane & 7)) * ASTR + ks * 16
                                     + ((lane & 8) ? 8 : 0)) * 2);
                mma16816(s[j], qf[ks], kf);
            }

        float tmax0 = -1e30f, tmax1 = -1e30f;
#pragma unroll
        for (int j = 0; j < 8; ++j) {
            s[j][0] *= 0.125f; s[j][1] *= 0.125f; s[j][2] *= 0.125f; s[j][3] *= 0.125f;
            tmax0 = fmaxf(tmax0, fmaxf(s[j][0], s[j][1]));
            tmax1 = fmaxf(tmax1, fmaxf(s[j][2], s[j][3]));
        }
        tmax0 = fmaxf(tmax0, __shfl_xor_sync(0xffffffffu, tmax0, 1));
        tmax0 = fmaxf(tmax0, __shfl_xor_sync(0xffffffffu, tmax0, 2));
        tmax1 = fmaxf(tmax1, __shfl_xor_sync(0xffffffffu, tmax1, 1));
        tmax1 = fmaxf(tmax1, __shfl_xor_sync(0xffffffffu, tmax1, 2));

        float nm0 = fmaxf(mrow0, tmax0), nm1 = fmaxf(mrow1, tmax1);
        float corr0 = __expf(mrow0 - nm0), corr1 = __expf(mrow1 - nm1);
        mrow0 = nm0; mrow1 = nm1;
#pragma unroll
        for (int j = 0; j < 8; ++j) {
            oacc[j][0] *= corr0; oacc[j][1] *= corr0;
            oacc[j][2] *= corr1; oacc[j][3] *= corr1;
        }

        float ps0 = 0.0f, ps1 = 0.0f;
        uint32_t aH[4][4], aL[4][4];
#pragma unroll
        for (int j = 0; j < 8; ++j) {
            float p0 = __expf(s[j][0] - nm0), p1 = __expf(s[j][1] - nm0);
            float p2 = __expf(s[j][2] - nm1), p3 = __expf(s[j][3] - nm1);
            ps0 += p0 + p1; ps1 += p2 + p3;
            __nv_bfloat16 h0 = __float2bfloat16(p0), h1 = __float2bfloat16(p1);
            __nv_bfloat16 h2 = __float2bfloat16(p2), h3 = __float2bfloat16(p3);
            const int jp = j >> 1, sel = (j & 1) * 2;
            aH[jp][sel + 0] = pkbf2(__bfloat162float(h0), __bfloat162float(h1));
            aH[jp][sel + 1] = pkbf2(__bfloat162float(h2), __bfloat162float(h3));
            aL[jp][sel + 0] = pkbf2(p0 - __bfloat162float(h0), p1 - __bfloat162float(h1));
            aL[jp][sel + 1] = pkbf2(p2 - __bfloat162float(h2), p3 - __bfloat162float(h3));
        }
        ps0 += __shfl_xor_sync(0xffffffffu, ps0, 1);
        ps0 += __shfl_xor_sync(0xffffffffu, ps0, 2);
        ps1 += __shfl_xor_sync(0xffffffffu, ps1, 1);
        ps1 += __shfl_xor_sync(0xffffffffu, ps1, 2);
        lrow0 = lrow0 * corr0 + ps0;
        lrow1 = lrow1 * corr1 + ps1;

#pragma unroll
        for (int jd = 0; jd < 8; ++jd)
#pragma unroll
            for (int ks = 0; ks < 4; ++ks) {
                uint32_t vh2[2], vl2[2];
                uint32_t ad = ((16 * ks + (lane & 15)) * ASTR + 8 * jd) * 2;
                ldsm_x2t(vh2, vhb + ad);
                ldsm_x2t(vl2, vlb + ad);
                mma16816(oacc[jd], aH[ks], vh2);
                mma16816(oacc[jd], aH[ks], vl2);
                mma16816(oacc[jd], aL[ks], vh2);
            }
    }

    const float inv0 = 1.0f / lrow0, inv1 = 1.0f / lrow1;
    const int er = lane >> 2, ec = (lane & 3) * 2;
    const size_t r0o = (rowbase + q0 + wq + er) * NQKV + coff;
    const size_t r1o = r0o + (size_t)8 * NQKV;
#pragma unroll
    for (int jd = 0; jd < 8; ++jd) {
        const int n = 8 * jd + ec;
        float v0 = oacc[jd][0] * inv0, v1 = oacc[jd][1] * inv0;
        float v2 = oacc[jd][2] * inv1, v3 = oacc[jd][3] * inv1;
        __nv_bfloat16 h0 = __float2bfloat16(v0), h1 = __float2bfloat16(v1);
        __nv_bfloat16 h2 = __float2bfloat16(v2), h3 = __float2bfloat16(v3);
        *(__nv_bfloat162*)&AOh[r0o + n] = __halves2bfloat162(h0, h1);
        *(__nv_bfloat162*)&AOh[r1o + n] = __halves2bfloat162(h2, h3);
        __nv_bfloat16 l0 = __float2bfloat16(v0 - __bfloat162float(h0));
        __nv_bfloat16 l1 = __float2bfloat16(v1 - __bfloat162float(h1));
        __nv_bfloat16 l2 = __float2bfloat16(v2 - __bfloat162float(h2));
        __nv_bfloat16 l3 = __float2bfloat16(v3 - __bfloat162float(h3));
        *(__nv_bfloat162*)&AOl[r0o + n] = __halves2bfloat162(l0, l1);
        *(__nv_bfloat162*)&AOl[r1o + n] = __halves2bfloat162(l2, l3);
    }
}

// -------------------- launch ---------------------------------------------------
extern "C" void kernel_launch(void* const* d_in, const int* in_sizes, int n_in,
                              void* d_out, int out_size) {
    const float* x  = (const float*)d_in[0];
    const float* Wq = (const float*)d_in[1];
    const float* bq = (const float*)d_in[2];
    const float* Wk = (const float*)d_in[3];
    const float* bk = (const float*)d_in[4];
    const float* Wv = (const float*)d_in[5];
    const float* bv = (const float*)d_in[6];
    const float* Wo = (const float*)d_in[7];
    const float* bo = (const float*)d_in[8];
    float* out = (float*)d_out;

    __nv_bfloat16 *xh, *xl, *qkvh, *qkvl, *aoh, *aol, *wch, *wcl, *woh, *wol;
    float* bcat;
    cudaGetSymbolAddress((void**)&xh,   g_xh);   cudaGetSymbolAddress((void**)&xl,   g_xl);
    cudaGetSymbolAddress((void**)&qkvh, g_qkvh); cudaGetSymbolAddress((void**)&qkvl, g_qkvl);
    cudaGetSymbolAddress((void**)&aoh,  g_aoh);  cudaGetSymbolAddress((void**)&aol,  g_aol);
    cudaGetSymbolAddress((void**)&wch,  g_wch);  cudaGetSymbolAddress((void**)&wcl,  g_wcl);
    cudaGetSymbolAddress((void**)&woh,  g_woh);  cudaGetSymbolAddress((void**)&wol,  g_wol);
    cudaGetSymbolAddress((void**)&bcat, g_bcat);

    cudaFuncSetAttribute(gemm_bf16x3<0>, cudaFuncAttributeMaxDynamicSharedMemorySize, GSM_TOTAL);
    cudaFuncSetAttribute(gemm_bf16x3<3>, cudaFuncAttributeMaxDynamicSharedMemorySize, GSM_TOTAL);

    // 1) split x into bf16 hi/lo; bias concat
    split_kernel<<<(NTOK * DMODEL / 2 + 255) / 256, 256>>>(x, xh, xl, NTOK * DMODEL / 2);
    bias_cat<<<(NCAT + 255) / 256, 256>>>(bq, bk, bv, bcat);

    // 2) transpose+split weights into concatenated buffer; Wo separately.
    dim3 tb(32, 8);
    transpose_split3<<<dim3(NQKV / 32, DMODEL / 32, 3), tb>>>(
        Wq, wch, wcl,
        Wk, wch + (size_t)512 * DMODEL,  wcl + (size_t)512 * DMODEL,
        Wv, wch + (size_t)1024 * DMODEL, wcl + (size_t)1024 * DMODEL,
        DMODEL, NQKV);
    transpose_split3<<<dim3(DMODEL / 32, NQKV / 32, 1), tb>>>(
        Wo, woh, wol, nullptr, nullptr, nullptr, nullptr, nullptr, nullptr, NQKV, DMODEL);

    // 3) fused QKV projection (mixed precision): Q,K tiles 1-product, V tiles 3
    dim3 gq(NCAT / 128, NTOK / 128);
    gemm_bf16x3<3><<<gq, 256, GSM_TOTAL>>>(xh, xl, wch, wcl, bcat,
                                           nullptr, qkvh, qkvl, DMODEL, NCAT);

    // 4) HMMA flash attention -> AO hi/lo
    dim3 ga(SEQ / 64, NHEAD, 8);
    attn_mma<<<ga, 128>>>(qkvh, qkvl, aoh, aol);

    // 5) output projection (fp32 out, bf16x3): [8192,512] @ [1024,512]^T + bo
    dim3 go(DMODEL / 128, NTOK / 128);
    gemm_bf16x3<0><<<go, 256, GSM_TOTAL>>>(aoh, aol, woh, wol, bo, out,
                                           nullptr, nullptr, NQKV, DMODEL);
}